// round 1
// baseline (speedup 1.0000x reference)
#include <cuda_runtime.h>
#include <cstdint>

#define T_STEPS 512
#define BATCH   2048
#define F_IN    64
#define HID     32
#define NGATE   128   // 4*HID
#define KTOT    96    // F_IN + HID
#define NS      8     // samples per CTA
#define NDUO    4     // NS/2

typedef unsigned long long ull;

__device__ __forceinline__ ull pack2(float lo, float hi) {
    ull r;
    asm("mov.b64 %0, {%1,%2};" : "=l"(r) : "f"(lo), "f"(hi));
    return r;
}
__device__ __forceinline__ void unpack2(ull p, float &lo, float &hi) {
    asm("mov.b64 {%0,%1}, %2;" : "=f"(lo), "=f"(hi) : "l"(p));
}
// packed f32x2 fma: d = a*b + c (lane-wise)
__device__ __forceinline__ ull fma2(ull a, ull b, ull c) {
    ull d;
    asm("fma.rn.f32x2 %0, %1, %2, %3;" : "=l"(d) : "l"(a), "l"(b), "l"(c));
    return d;
}

__device__ __forceinline__ float sigm(float x) {
    return 1.0f / (1.0f + __expf(-x));
}
// tanh(x) = 1 - 2/(exp(2x)+1); saturates cleanly at +-1 (no inf/inf NaN)
__device__ __forceinline__ float tanh_f(float x) {
    return 1.0f - 2.0f / (1.0f + __expf(2.0f * x));
}

__global__ void __launch_bounds__(128)
lstm_fused_kernel(const float* __restrict__ x,
                  const float* __restrict__ W_ih,
                  const float* __restrict__ W_hh,
                  const float* __restrict__ b_ih,
                  const float* __restrict__ b_hh,
                  const float* __restrict__ W_d,
                  const float* __restrict__ b_d,
                  float* __restrict__ out)
{
    // xq[duo][k] = { v_{s=2*duo}, v_{s=2*duo}, v_{s=2*duo+1}, v_{s=2*duo+1} }
    // k < 64: x features; k in [64,96): h (hidden) values
    __shared__ ulonglong2 xq[NDUO][KTOT];      // 6144 B
    __shared__ float      gbuf[NS][NGATE];     // 4096 B

    const int t   = threadIdx.x;
    const int rp  = t & 63;          // gate-row-pair id: rows (2rp, 2rp+1)
    const int grp = t >> 6;          // 0/1: which duo pair {2g, 2g+1}
    const int b0  = blockIdx.x * NS; // first sample of this CTA

    const int r0 = 2 * rp;
    const int r1 = 2 * rp + 1;

    // ---- load weights into packed registers: w[k] = {W[r0][k], W[r1][k]} ----
    ull w[KTOT];
#pragma unroll
    for (int k = 0; k < F_IN; k++)
        w[k] = pack2(W_ih[r0 * F_IN + k], W_ih[r1 * F_IN + k]);
#pragma unroll
    for (int k = 0; k < HID; k++)
        w[F_IN + k] = pack2(W_hh[r0 * HID + k], W_hh[r1 * HID + k]);
    const ull biasp = pack2(b_ih[r0] + b_hh[r0], b_ih[r1] + b_hh[r1]);

    // row pair (2rp,2rp+1) never straddles a 32-row gate block; gate = rp/16
    const bool is_tanh_gate = (rp >= 32) && (rp < 48);   // gate g (rows 64..95)

    // ---- phase-2 state mapping: thread owns cells (j, sA) and (j, sB) ----
    const int j  = t & 31;
    const int sA = t >> 5;       // 0..3
    const int sB = sA + 4;       // 4..7
    float cA = 0.0f, cB = 0.0f;

    // ---- x staging address math (shared by init + main loop) ----
    const int sP   = t >> 4;          // sample this thread stages (0..7)
    const int f0   = (4 * t) & 63;    // first feature it stages
    const int duoP = sP >> 1;
    const int lane = sP & 1;
    ull* xqf = (ull*)&xq[0][0];       // flat view: entry (duo*96 + k)*2 + lane

    // ---- initial staging: zero h region, stage x[t=0] ----
    for (int e = t; e < NDUO * HID * 2; e += 128) {
        int d  = e >> 6;          // duo
        int r  = e & 63;
        xqf[(d * KTOT + F_IN + (r >> 1)) * 2 + (r & 1)] = 0ULL;
    }
    {
        const float4 v = *reinterpret_cast<const float4*>(
            x + (size_t)b0 * F_IN + 4 * t);
        ull* base = &xqf[(duoP * KTOT) * 2 + lane];
        base[(f0 + 0) * 2] = pack2(v.x, v.x);
        base[(f0 + 1) * 2] = pack2(v.y, v.y);
        base[(f0 + 2) * 2] = pack2(v.z, v.z);
        base[(f0 + 3) * 2] = pack2(v.w, v.w);
    }
    __syncthreads();

    const int d0 = grp * 2;
    const int d1 = d0 + 1;

    for (int ts = 0; ts < T_STEPS; ts++) {
        // prefetch x for step ts+1 (hidden under this step's compute)
        float4 pf;
        const bool has_next = (ts + 1 < T_STEPS);
        if (has_next) {
            pf = *reinterpret_cast<const float4*>(
                x + (size_t)(ts + 1) * BATCH * F_IN + (size_t)b0 * F_IN + 4 * t);
        }

        // ---- phase 1: gates for rows (r0,r1), samples 2d0,2d0+1,2d1,2d1+1 ----
        ull a00 = biasp, a01 = biasp, a10 = biasp, a11 = biasp;
#pragma unroll
        for (int k = 0; k < KTOT; k++) {
            const ull wv = w[k];
            const ulonglong2 q0 = xq[d0][k];
            const ulonglong2 q1 = xq[d1][k];
            a00 = fma2(q0.x, wv, a00);
            a01 = fma2(q0.y, wv, a01);
            a10 = fma2(q1.x, wv, a10);
            a11 = fma2(q1.y, wv, a11);
        }

        // activations + store gates
        {
            float lo, hi;
            unpack2(a00, lo, hi);
            if (is_tanh_gate) { lo = tanh_f(lo); hi = tanh_f(hi); }
            else              { lo = sigm(lo);   hi = sigm(hi);   }
            *(float2*)&gbuf[2 * d0][r0] = make_float2(lo, hi);

            unpack2(a01, lo, hi);
            if (is_tanh_gate) { lo = tanh_f(lo); hi = tanh_f(hi); }
            else              { lo = sigm(lo);   hi = sigm(hi);   }
            *(float2*)&gbuf[2 * d0 + 1][r0] = make_float2(lo, hi);

            unpack2(a10, lo, hi);
            if (is_tanh_gate) { lo = tanh_f(lo); hi = tanh_f(hi); }
            else              { lo = sigm(lo);   hi = sigm(hi);   }
            *(float2*)&gbuf[2 * d1][r0] = make_float2(lo, hi);

            unpack2(a11, lo, hi);
            if (is_tanh_gate) { lo = tanh_f(lo); hi = tanh_f(hi); }
            else              { lo = sigm(lo);   hi = sigm(hi);   }
            *(float2*)&gbuf[2 * d1 + 1][r0] = make_float2(lo, hi);
        }
        __syncthreads();   // gates visible; all xq reads of step ts done

        // ---- phase 2: state update (2 cells per thread) ----
        {
            const float iA = gbuf[sA][j];
            const float fA = gbuf[sA][HID + j];
            const float gA = gbuf[sA][2 * HID + j];
            const float oA = gbuf[sA][3 * HID + j];
            cA = fA * cA + iA * gA;
            const float hA = oA * tanh_f(cA);
            xqf[((sA >> 1) * KTOT + F_IN + j) * 2 + (sA & 1)] = pack2(hA, hA);

            const float iB = gbuf[sB][j];
            const float fB = gbuf[sB][HID + j];
            const float gB = gbuf[sB][2 * HID + j];
            const float oB = gbuf[sB][3 * HID + j];
            cB = fB * cB + iB * gB;
            const float hB = oB * tanh_f(cB);
            xqf[((sB >> 1) * KTOT + F_IN + j) * 2 + (sB & 1)] = pack2(hB, hB);
        }

        // stage x_{ts+1}
        if (has_next) {
            ull* base = &xqf[(duoP * KTOT) * 2 + lane];
            base[(f0 + 0) * 2] = pack2(pf.x, pf.x);
            base[(f0 + 1) * 2] = pack2(pf.y, pf.y);
            base[(f0 + 2) * 2] = pack2(pf.z, pf.z);
            base[(f0 + 3) * 2] = pack2(pf.w, pf.w);
        }
        __syncthreads();   // xq ready for step ts+1
    }

    // ---- epilogue: out[b, a] = relu(h_T) @ W_d^T + b_d ----
    if (t < NS * 3) {
        const int s = t / 3;
        const int a = t % 3;
        float sum = b_d[a];
#pragma unroll
        for (int jj = 0; jj < HID; jj++) {
            // h stored duplicated; read the lower float of the (s&1) 8-byte lane
            float hv = ((const float*)&xq[s >> 1][F_IN + jj])[(s & 1) * 2];
            hv = fmaxf(hv, 0.0f);
            sum += hv * W_d[a * HID + jj];
        }
        out[(size_t)(b0 + s) * 3 + a] = sum;
    }
}

extern "C" void kernel_launch(void* const* d_in, const int* in_sizes, int n_in,
                              void* d_out, int out_size)
{
    const float* x    = (const float*)d_in[0];
    const float* W_ih = (const float*)d_in[1];
    const float* W_hh = (const float*)d_in[2];
    const float* b_ih = (const float*)d_in[3];
    const float* b_hh = (const float*)d_in[4];
    const float* W_d  = (const float*)d_in[5];
    const float* b_d  = (const float*)d_in[6];
    float* out = (float*)d_out;

    dim3 grid(BATCH / NS);   // 256 CTAs
    dim3 block(128);
    lstm_fused_kernel<<<grid, block>>>(x, W_ih, W_hh, b_ih, b_hh, W_d, b_d, out);
}

// round 2
// speedup vs baseline: 1.1038x; 1.1038x over previous
#include <cuda_runtime.h>
#include <cstdint>

#define T_STEPS 512
#define BATCH   2048
#define F_IN    64
#define HID     32
#define NGATE   128   // 4*HID
#define KK      48    // packed k pairs: (F_IN + HID)/2
#define NS      8     // samples per CTA

typedef unsigned long long ull;

__device__ __forceinline__ ull pack2(float lo, float hi) {
    ull r;
    asm("mov.b64 %0, {%1,%2};" : "=l"(r) : "f"(lo), "f"(hi));
    return r;
}
__device__ __forceinline__ void unpack2(ull p, float &lo, float &hi) {
    asm("mov.b64 {%0,%1}, %2;" : "=f"(lo), "=f"(hi) : "l"(p));
}
// packed f32x2 fma: d = a*b + c (lane-wise)
__device__ __forceinline__ ull fma2(ull a, ull b, ull c) {
    ull d;
    asm("fma.rn.f32x2 %0, %1, %2, %3;" : "=l"(d) : "l"(a), "l"(b), "l"(c));
    return d;
}

__device__ __forceinline__ float sigm(float x) {
    return 1.0f / (1.0f + __expf(-x));
}
// tanh(x) = 1 - 2/(exp(2x)+1); saturates cleanly at +-1
__device__ __forceinline__ float tanh_f(float x) {
    return 1.0f - 2.0f / (1.0f + __expf(2.0f * x));
}

__global__ void __launch_bounds__(128)
lstm_fused_kernel(const float* __restrict__ x,
                  const float* __restrict__ W_ih,
                  const float* __restrict__ W_hh,
                  const float* __restrict__ b_ih,
                  const float* __restrict__ b_hh,
                  const float* __restrict__ W_d,
                  const float* __restrict__ b_d,
                  float* __restrict__ out)
{
    // xsh[kk][s] = { v_s[2kk], v_s[2kk+1] }  (v = concat(x_feat[64], h[32]))
    // kk in [0,32): x features; kk in [32,48): hidden state
    __shared__ ull   xsh[KK][NS];        // 3072 B
    __shared__ float gbuf[NS][NGATE];    // 4096 B

    const int t  = threadIdx.x;
    const int r  = t;                    // this thread's gate row (0..127)
    const int b0 = blockIdx.x * NS;

    // ---- weights packed along k: 48 ull = 96 regs ----
    ull w[KK];
#pragma unroll
    for (int kk = 0; kk < F_IN / 2; kk++)
        w[kk] = pack2(W_ih[r * F_IN + 2 * kk], W_ih[r * F_IN + 2 * kk + 1]);
#pragma unroll
    for (int kk = 0; kk < HID / 2; kk++)
        w[F_IN / 2 + kk] = pack2(W_hh[r * HID + 2 * kk], W_hh[r * HID + 2 * kk + 1]);
    const ull biasp = pack2(b_ih[r] + b_hh[r], 0.0f);

    const bool is_tanh_gate = (r >= 2 * HID) && (r < 3 * HID);  // g-gate rows

    // ---- phase-2 state mapping: thread owns cells (j, sA) and (j, sB) ----
    const int j  = t & 31;
    const int sA = t >> 5;      // 0..3
    const int sB = sA + 4;      // 4..7
    float cA = 0.0f, cB = 0.0f;
    const int   kkh  = F_IN / 2 + (j >> 1);   // xsh row holding h_j
    const int   half = j & 1;
    float* xf = (float*)&xsh[0][0];           // float idx = (kk*NS + s)*2 + half

    // ---- x staging mapping: thread stages sample sP, features f0..f0+3 ----
    const int sP  = t >> 4;
    const int kk0 = (t & 15) * 2;

    // ---- init: zero h region, stage x[t=0] ----
    // h region = 16 kk rows x 8 samples = 128 entries, one per thread
    xsh[F_IN / 2 + (t >> 3)][t & 7] = 0ULL;
    {
        const float4 v = *reinterpret_cast<const float4*>(
            x + (size_t)b0 * F_IN + 4 * t);
        xsh[kk0][sP]     = pack2(v.x, v.y);
        xsh[kk0 + 1][sP] = pack2(v.z, v.w);
    }
    __syncthreads();

    for (int ts = 0; ts < T_STEPS; ts++) {
        // prefetch x for step ts+1 (hidden under this step's compute)
        float4 pf;
        const bool has_next = (ts + 1 < T_STEPS);
        if (has_next) {
            pf = *reinterpret_cast<const float4*>(
                x + ((size_t)(ts + 1) * BATCH + b0) * F_IN + 4 * t);
        }

        // ---- phase 1: gate row r for all 8 samples ----
        ull a0 = biasp, a1 = biasp, a2 = biasp, a3 = biasp;
        ull a4 = biasp, a5 = biasp, a6 = biasp, a7 = biasp;
#pragma unroll
        for (int kk = 0; kk < KK; kk++) {
            const ull wv = w[kk];
            const ulonglong2 qa = *reinterpret_cast<const ulonglong2*>(&xsh[kk][0]);
            const ulonglong2 qb = *reinterpret_cast<const ulonglong2*>(&xsh[kk][2]);
            const ulonglong2 qc = *reinterpret_cast<const ulonglong2*>(&xsh[kk][4]);
            const ulonglong2 qd = *reinterpret_cast<const ulonglong2*>(&xsh[kk][6]);
            a0 = fma2(qa.x, wv, a0);
            a1 = fma2(qa.y, wv, a1);
            a2 = fma2(qb.x, wv, a2);
            a3 = fma2(qb.y, wv, a3);
            a4 = fma2(qc.x, wv, a4);
            a5 = fma2(qc.y, wv, a5);
            a6 = fma2(qd.x, wv, a6);
            a7 = fma2(qd.y, wv, a7);
        }

        // horizontal reduce + activation + store gates
        {
            float lo, hi, g;
            ull acc[8] = {a0, a1, a2, a3, a4, a5, a6, a7};
#pragma unroll
            for (int s = 0; s < NS; s++) {
                unpack2(acc[s], lo, hi);
                g = lo + hi;
                g = is_tanh_gate ? tanh_f(g) : sigm(g);
                gbuf[s][r] = g;
            }
        }
        __syncthreads();   // gates visible; all xsh reads of step ts done

        // ---- phase 2: state update (2 cells per thread) ----
        {
            const float iA = gbuf[sA][j];
            const float fA = gbuf[sA][HID + j];
            const float gA = gbuf[sA][2 * HID + j];
            const float oA = gbuf[sA][3 * HID + j];
            cA = fA * cA + iA * gA;
            const float hA = oA * tanh_f(cA);
            xf[(kkh * NS + sA) * 2 + half] = hA;

            const float iB = gbuf[sB][j];
            const float fB = gbuf[sB][HID + j];
            const float gB = gbuf[sB][2 * HID + j];
            const float oB = gbuf[sB][3 * HID + j];
            cB = fB * cB + iB * gB;
            const float hB = oB * tanh_f(cB);
            xf[(kkh * NS + sB) * 2 + half] = hB;
        }

        // stage x_{ts+1}
        if (has_next) {
            xsh[kk0][sP]     = pack2(pf.x, pf.y);
            xsh[kk0 + 1][sP] = pack2(pf.z, pf.w);
        }
        __syncthreads();   // xsh ready for step ts+1
    }

    // ---- epilogue: out[b, a] = relu(h_T) @ W_d^T + b_d ----
    if (t < NS * 3) {
        const int s = t / 3;
        const int a = t % 3;
        float sum = b_d[a];
#pragma unroll
        for (int jj = 0; jj < HID; jj++) {
            float hv = xf[((F_IN / 2 + (jj >> 1)) * NS + s) * 2 + (jj & 1)];
            hv = fmaxf(hv, 0.0f);
            sum += hv * W_d[a * HID + jj];
        }
        out[(size_t)(b0 + s) * 3 + a] = sum;
    }
}

extern "C" void kernel_launch(void* const* d_in, const int* in_sizes, int n_in,
                              void* d_out, int out_size)
{
    const float* x    = (const float*)d_in[0];
    const float* W_ih = (const float*)d_in[1];
    const float* W_hh = (const float*)d_in[2];
    const float* b_ih = (const float*)d_in[3];
    const float* b_hh = (const float*)d_in[4];
    const float* W_d  = (const float*)d_in[5];
    const float* b_d  = (const float*)d_in[6];
    float* out = (float*)d_out;

    dim3 grid(BATCH / NS);   // 256 CTAs
    dim3 block(128);
    lstm_fused_kernel<<<grid, block>>>(x, W_ih, W_hh, b_ih, b_hh, W_d, b_d, out);
}

// round 3
// speedup vs baseline: 1.1843x; 1.0730x over previous
#include <cuda_runtime.h>
#include <cstdint>

#define T_STEPS 512
#define BATCH   2048
#define F_IN    64
#define HID     32
#define NGATE   128   // 4*HID
#define NSB     4     // samples per CTA in recurrent kernel

typedef unsigned long long ull;

// x_proj[t][b][g] scratch: 512*2048*128 floats = 512 MB
__device__ float g_xproj[(size_t)T_STEPS * BATCH * NGATE];

__device__ __forceinline__ ull pack2(float lo, float hi) {
    ull r;
    asm("mov.b64 %0, {%1,%2};" : "=l"(r) : "f"(lo), "f"(hi));
    return r;
}
__device__ __forceinline__ void unpack2(ull p, float &lo, float &hi) {
    asm("mov.b64 {%0,%1}, %2;" : "=f"(lo), "=f"(hi) : "l"(p));
}
// packed f32x2 fma: d = a*b + c (lane-wise)
__device__ __forceinline__ ull fma2(ull a, ull b, ull c) {
    ull d;
    asm("fma.rn.f32x2 %0, %1, %2, %3;" : "=l"(d) : "l"(a), "l"(b), "l"(c));
    return d;
}

__device__ __forceinline__ float sigm(float x) {
    return 1.0f / (1.0f + __expf(-x));
}
// tanh(x) = 1 - 2/(exp(2x)+1); saturates cleanly at +-1
__device__ __forceinline__ float tanh_f(float x) {
    return 1.0f - 2.0f / (1.0f + __expf(2.0f * x));
}

// ============================================================================
// Kernel A: x_proj = x @ W_ih^T + (b_ih + b_hh)   -- [1M, 64] x [64, 128]
// One CTA = 64 sample rows; thread g owns gate row g with weights in regs.
// ============================================================================
__global__ void __launch_bounds__(128)
xproj_kernel(const float* __restrict__ x,
             const float* __restrict__ W_ih,
             const float* __restrict__ b_ih,
             const float* __restrict__ b_hh)
{
    __shared__ float xs[64][64];   // 16 KB tile of x rows

    const int t = threadIdx.x;
    const int g = t;                              // gate row 0..127
    const size_t row0 = (size_t)blockIdx.x * 64;  // first sample row

    // weights packed along k: 32 ull = 64 regs
    ull w[32];
#pragma unroll
    for (int kk = 0; kk < 32; kk++)
        w[kk] = pack2(W_ih[g * F_IN + 2 * kk], W_ih[g * F_IN + 2 * kk + 1]);
    const float bsum = b_ih[g] + b_hh[g];
    const ull binit = pack2(bsum, 0.0f);

    // stage tile: 64 rows x 64 floats = 1024 float4, 8 per thread, coalesced
    {
        const float4* xg = reinterpret_cast<const float4*>(x + row0 * F_IN);
        float4* xsf = reinterpret_cast<float4*>(&xs[0][0]);
#pragma unroll
        for (int it = 0; it < 8; it++) {
            const int f4 = t + 128 * it;
            xsf[f4] = xg[f4];
        }
    }
    __syncthreads();

    float* outp = g_xproj + row0 * NGATE + g;
#pragma unroll 1
    for (int s = 0; s < 64; s += 4) {
        ull a0 = binit, a1 = binit, a2 = binit, a3 = binit;
#pragma unroll
        for (int kk2 = 0; kk2 < 16; kk2++) {
            const ulonglong2 q0 = *reinterpret_cast<const ulonglong2*>(&xs[s + 0][kk2 * 4]);
            const ulonglong2 q1 = *reinterpret_cast<const ulonglong2*>(&xs[s + 1][kk2 * 4]);
            const ulonglong2 q2 = *reinterpret_cast<const ulonglong2*>(&xs[s + 2][kk2 * 4]);
            const ulonglong2 q3 = *reinterpret_cast<const ulonglong2*>(&xs[s + 3][kk2 * 4]);
            const ull we = w[2 * kk2], wo = w[2 * kk2 + 1];
            a0 = fma2(q0.x, we, a0);  a0 = fma2(q0.y, wo, a0);
            a1 = fma2(q1.x, we, a1);  a1 = fma2(q1.y, wo, a1);
            a2 = fma2(q2.x, we, a2);  a2 = fma2(q2.y, wo, a2);
            a3 = fma2(q3.x, we, a3);  a3 = fma2(q3.y, wo, a3);
        }
        float lo, hi;
        unpack2(a0, lo, hi);  outp[(size_t)(s + 0) * NGATE] = lo + hi;
        unpack2(a1, lo, hi);  outp[(size_t)(s + 1) * NGATE] = lo + hi;
        unpack2(a2, lo, hi);  outp[(size_t)(s + 2) * NGATE] = lo + hi;
        unpack2(a3, lo, hi);  outp[(size_t)(s + 3) * NGATE] = lo + hi;
    }
}

// ============================================================================
// Kernel B: recurrence. CTA = 4 samples, 128 threads (thread = gate row).
// gates = x_proj[ts] + h @ W_hh^T ; state update thread-local per cell.
// ============================================================================
__global__ void __launch_bounds__(128)
recur_kernel(const float* __restrict__ W_hh,
             const float* __restrict__ W_d,
             const float* __restrict__ b_d,
             float* __restrict__ out)
{
    __shared__ ull   hsh[HID / 2][NSB];    // h packed pairs: 512 B
    __shared__ float gbuf[NSB][NGATE];     // 2 KB

    const int t  = threadIdx.x;
    const int r  = t;                      // gate row
    const int b0 = blockIdx.x * NSB;

    // W_hh packed along k: 16 ull = 32 regs
    ull w[16];
#pragma unroll
    for (int kk = 0; kk < 16; kk++)
        w[kk] = pack2(W_hh[r * HID + 2 * kk], W_hh[r * HID + 2 * kk + 1]);

    const bool is_tanh_gate = (r >= 2 * HID) && (r < 3 * HID);

    // phase-2 mapping: thread owns cell (j, s2)
    const int j  = t & 31;
    const int s2 = t >> 5;       // 0..3
    float c = 0.0f;
    float* hf = (float*)&hsh[0][0];        // idx (kk*NSB + s)*2 + half
    const int kkh = j >> 1, half = j & 1;

    // zero h
    if (t < (HID / 2) * NSB) ((ull*)hsh)[t] = 0ULL;

    // x_proj pointer for this thread: [ts][b0+s][r]
    const float* xpp = g_xproj + ((size_t)0 * BATCH + b0) * NGATE + r;
    const size_t step_stride = (size_t)BATCH * NGATE;

    float xp0 = xpp[0 * NGATE];
    float xp1 = xpp[1 * NGATE];
    float xp2 = xpp[2 * NGATE];
    float xp3 = xpp[3 * NGATE];
    __syncthreads();

    for (int ts = 0; ts < T_STEPS; ts++) {
        // prefetch next step's x_proj (hidden under compute)
        float xn0, xn1, xn2, xn3;
        const bool has_next = (ts + 1 < T_STEPS);
        if (has_next) {
            const float* xn = xpp + (size_t)(ts + 1) * step_stride;
            xn0 = xn[0 * NGATE];
            xn1 = xn[1 * NGATE];
            xn2 = xn[2 * NGATE];
            xn3 = xn[3 * NGATE];
        }

        // phase 1: gate row r for 4 samples
        ull a0 = pack2(xp0, 0.0f);
        ull a1 = pack2(xp1, 0.0f);
        ull a2 = pack2(xp2, 0.0f);
        ull a3 = pack2(xp3, 0.0f);
#pragma unroll
        for (int kk = 0; kk < 16; kk++) {
            const ull wv = w[kk];
            const ulonglong2 qa = *reinterpret_cast<const ulonglong2*>(&hsh[kk][0]);
            const ulonglong2 qb = *reinterpret_cast<const ulonglong2*>(&hsh[kk][2]);
            a0 = fma2(qa.x, wv, a0);
            a1 = fma2(qa.y, wv, a1);
            a2 = fma2(qb.x, wv, a2);
            a3 = fma2(qb.y, wv, a3);
        }
        {
            float lo, hi, gv;
            unpack2(a0, lo, hi); gv = lo + hi;
            gbuf[0][r] = is_tanh_gate ? tanh_f(gv) : sigm(gv);
            unpack2(a1, lo, hi); gv = lo + hi;
            gbuf[1][r] = is_tanh_gate ? tanh_f(gv) : sigm(gv);
            unpack2(a2, lo, hi); gv = lo + hi;
            gbuf[2][r] = is_tanh_gate ? tanh_f(gv) : sigm(gv);
            unpack2(a3, lo, hi); gv = lo + hi;
            gbuf[3][r] = is_tanh_gate ? tanh_f(gv) : sigm(gv);
        }
        __syncthreads();   // gates visible; hsh reads of this step done

        // phase 2: one cell per thread
        {
            const float ig = gbuf[s2][j];
            const float fg = gbuf[s2][HID + j];
            const float gg = gbuf[s2][2 * HID + j];
            const float og = gbuf[s2][3 * HID + j];
            c = fg * c + ig * gg;
            const float h = og * tanh_f(c);
            hf[(kkh * NSB + s2) * 2 + half] = h;
        }

        if (has_next) { xp0 = xn0; xp1 = xn1; xp2 = xn2; xp3 = xn3; }
        __syncthreads();   // hsh ready for next step
    }

    // epilogue: out[b, a] = relu(h_T) @ W_d^T + b_d
    if (t < NSB * 3) {
        const int s = t / 3;
        const int a = t % 3;
        float sum = b_d[a];
#pragma unroll
        for (int jj = 0; jj < HID; jj++) {
            float hv = hf[((jj >> 1) * NSB + s) * 2 + (jj & 1)];
            hv = fmaxf(hv, 0.0f);
            sum += hv * W_d[a * HID + jj];
        }
        out[(size_t)(b0 + s) * 3 + a] = sum;
    }
}

extern "C" void kernel_launch(void* const* d_in, const int* in_sizes, int n_in,
                              void* d_out, int out_size)
{
    const float* x    = (const float*)d_in[0];
    const float* W_ih = (const float*)d_in[1];
    const float* W_hh = (const float*)d_in[2];
    const float* b_ih = (const float*)d_in[3];
    const float* b_hh = (const float*)d_in[4];
    const float* W_d  = (const float*)d_in[5];
    const float* b_d  = (const float*)d_in[6];
    float* out = (float*)d_out;

    // Kernel A: x_proj GEMM over all timesteps (no recurrence)
    {
        dim3 grid((T_STEPS * BATCH) / 64);   // 16384 CTAs
        dim3 block(128);
        xproj_kernel<<<grid, block>>>(x, W_ih, b_ih, b_hh);
    }
    // Kernel B: sequential LSTM recurrence + decode head
    {
        dim3 grid(BATCH / NSB);              // 512 CTAs
        dim3 block(128);
        recur_kernel<<<grid, block>>>(W_hh, W_d, b_d, out);
    }
}

// round 4
// speedup vs baseline: 1.3536x; 1.1429x over previous
#include <cuda_runtime.h>
#include <cstdint>

#define T_STEPS 512
#define BATCH   2048
#define F_IN    64
#define HID     32
#define NGATE   128   // 4*HID
#define NSB     2     // samples per CTA in recurrent kernel

typedef unsigned long long ull;

// x_proj[t][b][g] scratch: 512*2048*128 floats = 512 MB
__device__ float g_xproj[(size_t)T_STEPS * BATCH * NGATE];

__device__ __forceinline__ ull pack2(float lo, float hi) {
    ull r;
    asm("mov.b64 %0, {%1,%2};" : "=l"(r) : "f"(lo), "f"(hi));
    return r;
}
__device__ __forceinline__ void unpack2(ull p, float &lo, float &hi) {
    asm("mov.b64 {%0,%1}, %2;" : "=f"(lo), "=f"(hi) : "l"(p));
}
// packed f32x2 fma: d = a*b + c (lane-wise)
__device__ __forceinline__ ull fma2(ull a, ull b, ull c) {
    ull d;
    asm("fma.rn.f32x2 %0, %1, %2, %3;" : "=l"(d) : "l"(a), "l"(b), "l"(c));
    return d;
}

__device__ __forceinline__ float tanh_fast(float x) {
    float y;
    asm("tanh.approx.f32 %0, %1;" : "=f"(y) : "f"(x));
    return y;
}
__device__ __forceinline__ float sigm_fast(float x) {
    return fmaf(0.5f, tanh_fast(0.5f * x), 0.5f);
}

// ============================================================================
// Kernel A: x_proj = x @ W_ih^T + (b_ih + b_hh)   -- [1M, 64] x [64, 128]
// Classic register-tiled GEMM: CTA tile 64 samples x 128 gates, thread tile
// 8 samples x 8 gates (4 gate-pair accumulators). Weights AND x from smem:
// per k: 6 LDS.128 feed 32 FFMA2.
// ============================================================================
#define XTM 64    // samples per CTA
#define XKC 32    // k-chunk

__global__ void __launch_bounds__(128)
xproj_kernel(const float* __restrict__ x,
             const float* __restrict__ W_ih,
             const float* __restrict__ b_ih,
             const float* __restrict__ b_hh)
{
    // xd[k][s] = {x_s_k, x_s_k} duplicated duo; wp[k][gp] = {W[2gp][k], W[2gp+1][k]}
    __shared__ __align__(16) ull xd[XKC][XTM + 2];
    __shared__ __align__(16) ull wp[XKC][64 + 2];

    const int t  = threadIdx.x;
    const int tx = t & 15;               // gate group: gp = tx*4 .. tx*4+3
    const int ty = t >> 4;               // sample group: s = ty*8 .. ty*8+7
    const size_t row0 = (size_t)blockIdx.x * XTM;

    // accumulators init with bias pairs
    ull acc[8][4];
    {
        ull bp[4];
#pragma unroll
        for (int p = 0; p < 4; p++) {
            const int g0 = tx * 8 + 2 * p;
            bp[p] = pack2(b_ih[g0] + b_hh[g0], b_ih[g0 + 1] + b_hh[g0 + 1]);
        }
#pragma unroll
        for (int s = 0; s < 8; s++)
#pragma unroll
            for (int p = 0; p < 4; p++)
                acc[s][p] = bp[p];
    }

    const int kq = t & 7;     // staging: k-quad
    const int sb = t >> 3;    // staging: sample base (0..15)

    for (int kb = 0; kb < F_IN; kb += XKC) {
        __syncthreads();   // previous chunk's reads done before overwrite

        // stage xd: 32k x 64s duplicated duos
#pragma unroll
        for (int rep = 0; rep < 4; rep++) {
            const int s = sb + rep * 16;
            const float4 v = *reinterpret_cast<const float4*>(
                x + (row0 + s) * F_IN + kb + kq * 4);
            xd[kq * 4 + 0][s] = pack2(v.x, v.x);
            xd[kq * 4 + 1][s] = pack2(v.y, v.y);
            xd[kq * 4 + 2][s] = pack2(v.z, v.z);
            xd[kq * 4 + 3][s] = pack2(v.w, v.w);
        }
        // stage wp: 32k x 64 gate-pairs
#pragma unroll
        for (int rep = 0; rep < 16; rep++) {
            const int idx = t + 128 * rep;
            const int k   = idx >> 6;
            const int gp  = idx & 63;
            wp[k][gp] = pack2(W_ih[(2 * gp) * F_IN + kb + k],
                              W_ih[(2 * gp + 1) * F_IN + kb + k]);
        }
        __syncthreads();

#pragma unroll 8
        for (int k = 0; k < XKC; k++) {
            const ulonglong2 bq0 = *reinterpret_cast<const ulonglong2*>(&wp[k][tx * 4]);
            const ulonglong2 bq1 = *reinterpret_cast<const ulonglong2*>(&wp[k][tx * 4 + 2]);
            const ulonglong2 a01 = *reinterpret_cast<const ulonglong2*>(&xd[k][ty * 8]);
            const ulonglong2 a23 = *reinterpret_cast<const ulonglong2*>(&xd[k][ty * 8 + 2]);
            const ulonglong2 a45 = *reinterpret_cast<const ulonglong2*>(&xd[k][ty * 8 + 4]);
            const ulonglong2 a67 = *reinterpret_cast<const ulonglong2*>(&xd[k][ty * 8 + 6]);
            const ull av[8] = {a01.x, a01.y, a23.x, a23.y, a45.x, a45.y, a67.x, a67.y};
#pragma unroll
            for (int s = 0; s < 8; s++) {
                acc[s][0] = fma2(av[s], bq0.x, acc[s][0]);
                acc[s][1] = fma2(av[s], bq0.y, acc[s][1]);
                acc[s][2] = fma2(av[s], bq1.x, acc[s][2]);
                acc[s][3] = fma2(av[s], bq1.y, acc[s][3]);
            }
        }
    }

    // writeout: 8 samples x 8 gates per thread
#pragma unroll
    for (int s = 0; s < 8; s++) {
        float o[8];
#pragma unroll
        for (int p = 0; p < 4; p++)
            unpack2(acc[s][p], o[2 * p], o[2 * p + 1]);
        float* op = g_xproj + (row0 + ty * 8 + s) * NGATE + tx * 8;
        *reinterpret_cast<float4*>(op)     = make_float4(o[0], o[1], o[2], o[3]);
        *reinterpret_cast<float4*>(op + 4) = make_float4(o[4], o[5], o[6], o[7]);
    }
}

// ============================================================================
// Kernel B: recurrence. 64-thread CTA, 2 samples, thread owns gate rows
// (t, t+64). grid=1024 -> ~7 resident CTAs/SM for latency hiding.
// ============================================================================
__global__ void __launch_bounds__(64)
recur_kernel(const float* __restrict__ W_hh,
             const float* __restrict__ W_d,
             const float* __restrict__ b_d,
             float* __restrict__ out)
{
    __shared__ ull   hsh[HID / 2][NSB];    // h pairs x samples: 256 B
    __shared__ float gbuf[NSB][NGATE];     // 1 KB

    const int t  = threadIdx.x;            // 0..63
    const int r0 = t;
    const int r1 = t + 64;
    const int b0 = blockIdx.x * NSB;

    // W_hh rows r0, r1 packed along k: 32 ull = 64 regs
    ull w0[16], w1[16];
#pragma unroll
    for (int kk = 0; kk < 16; kk++) {
        w0[kk] = pack2(W_hh[r0 * HID + 2 * kk], W_hh[r0 * HID + 2 * kk + 1]);
        w1[kk] = pack2(W_hh[r1 * HID + 2 * kk], W_hh[r1 * HID + 2 * kk + 1]);
    }
    const bool r1_tanh = (t < 32);   // r1 in [64,96) = g-gate

    // phase-2 mapping: thread owns cell (j, s2)
    const int j  = t & 31;
    const int s2 = t >> 5;
    float c = 0.0f;

    // zero h (32 ull entries, one per thread t<32)
    if (t < (HID / 2) * NSB) ((ull*)hsh)[t] = 0ULL;

    const float* xpp = g_xproj + (size_t)b0 * NGATE;
    const size_t step_stride = (size_t)BATCH * NGATE;

    float xp00 = xpp[r0];
    float xp01 = xpp[NGATE + r0];
    float xp10 = xpp[r1];
    float xp11 = xpp[NGATE + r1];
    __syncthreads();

    for (int ts = 0; ts < T_STEPS; ts++) {
        // prefetch next step's x_proj
        float xn00, xn01, xn10, xn11;
        const bool has_next = (ts + 1 < T_STEPS);
        if (has_next) {
            const float* xn = xpp + (size_t)(ts + 1) * step_stride;
            xn00 = xn[r0];
            xn01 = xn[NGATE + r0];
            xn10 = xn[r1];
            xn11 = xn[NGATE + r1];
        }

        // phase 1: rows r0,r1 x samples 0,1 (k packed in pairs)
        ull a00 = pack2(xp00, 0.0f);
        ull a01 = pack2(xp01, 0.0f);
        ull a10 = pack2(xp10, 0.0f);
        ull a11 = pack2(xp11, 0.0f);
#pragma unroll
        for (int kk = 0; kk < 16; kk++) {
            const ulonglong2 hq = *reinterpret_cast<const ulonglong2*>(&hsh[kk][0]);
            a00 = fma2(hq.x, w0[kk], a00);
            a01 = fma2(hq.y, w0[kk], a01);
            a10 = fma2(hq.x, w1[kk], a10);
            a11 = fma2(hq.y, w1[kk], a11);
        }
        {
            float lo, hi, v;
            unpack2(a00, lo, hi); v = lo + hi;
            gbuf[0][r0] = sigm_fast(v);
            unpack2(a01, lo, hi); v = lo + hi;
            gbuf[1][r0] = sigm_fast(v);
            unpack2(a10, lo, hi); v = lo + hi;
            gbuf[0][r1] = r1_tanh ? tanh_fast(v) : sigm_fast(v);
            unpack2(a11, lo, hi); v = lo + hi;
            gbuf[1][r1] = r1_tanh ? tanh_fast(v) : sigm_fast(v);
        }
        __syncthreads();   // gates visible; hsh reads of this step done

        // phase 2: one cell per thread
        {
            const float ig = gbuf[s2][j];
            const float fg = gbuf[s2][HID + j];
            const float gg = gbuf[s2][2 * HID + j];
            const float og = gbuf[s2][3 * HID + j];
            c = fg * c + ig * gg;
            const float h = og * tanh_fast(c);
            ((float*)&hsh[j >> 1][s2])[j & 1] = h;
        }

        if (has_next) { xp00 = xn00; xp01 = xn01; xp10 = xn10; xp11 = xn11; }
        __syncthreads();   // hsh ready for next step
    }

    // epilogue: out[b, a] = relu(h_T) @ W_d^T + b_d
    if (t < NSB * 3) {
        const int s = t / 3;
        const int a = t % 3;
        float sum = b_d[a];
#pragma unroll
        for (int jj = 0; jj < HID; jj++) {
            float hv = ((const float*)&hsh[jj >> 1][s])[jj & 1];
            hv = fmaxf(hv, 0.0f);
            sum += hv * W_d[a * HID + jj];
        }
        out[(size_t)(b0 + s) * 3 + a] = sum;
    }
}

extern "C" void kernel_launch(void* const* d_in, const int* in_sizes, int n_in,
                              void* d_out, int out_size)
{
    const float* x    = (const float*)d_in[0];
    const float* W_ih = (const float*)d_in[1];
    const float* W_hh = (const float*)d_in[2];
    const float* b_ih = (const float*)d_in[3];
    const float* b_hh = (const float*)d_in[4];
    const float* W_d  = (const float*)d_in[5];
    const float* b_d  = (const float*)d_in[6];
    float* out = (float*)d_out;

    // Kernel A: x_proj GEMM over all timesteps (no recurrence)
    {
        dim3 grid((T_STEPS * BATCH) / XTM);   // 16384 CTAs
        dim3 block(128);
        xproj_kernel<<<grid, block>>>(x, W_ih, b_ih, b_hh);
    }
    // Kernel B: sequential LSTM recurrence + decode head
    {
        dim3 grid(BATCH / NSB);               // 1024 CTAs
        dim3 block(64);
        recur_kernel<<<grid, block>>>(W_hh, W_d, b_d, out);
    }
}

// round 5
// speedup vs baseline: 1.9160x; 1.4155x over previous
#include <cuda_runtime.h>
#include <cstdint>

#define T_STEPS 512
#define BATCH   2048
#define F_IN    64
#define HID     32
#define NGATE   128   // 4*HID

typedef unsigned long long ull;

// x_proj[t][b][g] scratch: 512*2048*128 floats = 512 MB
__device__ float g_xproj[(size_t)T_STEPS * BATCH * NGATE];

__device__ __forceinline__ ull pack2(float lo, float hi) {
    ull r;
    asm("mov.b64 %0, {%1,%2};" : "=l"(r) : "f"(lo), "f"(hi));
    return r;
}
__device__ __forceinline__ void unpack2(ull p, float &lo, float &hi) {
    asm("mov.b64 {%0,%1}, %2;" : "=f"(lo), "=f"(hi) : "l"(p));
}
// packed f32x2 fma: d = a*b + c (lane-wise)
__device__ __forceinline__ ull fma2(ull a, ull b, ull c) {
    ull d;
    asm("fma.rn.f32x2 %0, %1, %2, %3;" : "=l"(d) : "l"(a), "l"(b), "l"(c));
    return d;
}

__device__ __forceinline__ float tanh_fast(float x) {
    float y;
    asm("tanh.approx.f32 %0, %1;" : "=f"(y) : "f"(x));
    return y;
}
__device__ __forceinline__ float sigm_fast(float x) {
    return fmaf(0.5f, tanh_fast(0.5f * x), 0.5f);
}

// ============================================================================
// Kernel A: x_proj = x @ W_ih^T + (b_ih + b_hh)   -- [1M, 64] x [64, 128]
// k lives in the f32x2 lanes: acc = {sum over even k, sum over odd k}.
// Both x and W staged with COALESCED float4 loads, natural row-major as ull
// k-pairs. CTA tile: 64 samples x 128 gates (256 thr); thread tile 4s x 8g.
// ============================================================================
#define XS   64     // samples per CTA
#define WPIT 34     // ull pitch of wrow/xrow rows (32 data + 2 pad)

__global__ void __launch_bounds__(256)
xproj_kernel(const float* __restrict__ x,
             const float* __restrict__ W_ih,
             const float* __restrict__ b_ih,
             const float* __restrict__ b_hh)
{
    __shared__ __align__(16) ull wrow[NGATE * WPIT];  // 34816 B
    __shared__ __align__(16) ull xrow[XS * WPIT];     // 17408 B

    const int t  = threadIdx.x;
    const int tx = t & 15;               // gates: tx + 16p, p=0..7
    const int ty = t >> 4;               // samples: ty*4 .. ty*4+3
    const size_t row0 = (size_t)blockIdx.x * XS;

    // ---- stage W (32 KB) coalesced: 8 float4/thread ----
    {
        const float4* wg = reinterpret_cast<const float4*>(W_ih);
#pragma unroll
        for (int i = 0; i < 8; i++) {
            const int idx = t + 256 * i;      // float4 index, g-major
            const int g = idx >> 4;
            const int c = idx & 15;
            const float4 v = wg[idx];
            *reinterpret_cast<ulonglong2*>(&wrow[g * WPIT + 2 * c]) =
                make_ulonglong2(pack2(v.x, v.y), pack2(v.z, v.w));
        }
    }
    // ---- stage x tile (16 KB) coalesced: 4 float4/thread ----
    {
        const float4* xg = reinterpret_cast<const float4*>(x + row0 * F_IN);
#pragma unroll
        for (int i = 0; i < 4; i++) {
            const int idx = t + 256 * i;
            const int s = idx >> 4;
            const int c = idx & 15;
            const float4 v = xg[idx];
            *reinterpret_cast<ulonglong2*>(&xrow[s * WPIT + 2 * c]) =
                make_ulonglong2(pack2(v.x, v.y), pack2(v.z, v.w));
        }
    }

    // ---- acc init with bias in lo lane ----
    ull acc[4][8];
    {
#pragma unroll
        for (int p = 0; p < 8; p++) {
            const int g = tx + 16 * p;
            const ull b = pack2(b_ih[g] + b_hh[g], 0.0f);
#pragma unroll
            for (int q = 0; q < 4; q++) acc[q][p] = b;
        }
    }
    __syncthreads();

    // ---- main loop: per 2 kk: 12 LDS.128 feed 64 FFMA2 ----
#pragma unroll 4
    for (int kk = 0; kk < 32; kk += 2) {
        ulonglong2 xq[4], wq[8];
#pragma unroll
        for (int q = 0; q < 4; q++)
            xq[q] = *reinterpret_cast<const ulonglong2*>(
                &xrow[(ty * 4 + q) * WPIT + kk]);
#pragma unroll
        for (int p = 0; p < 8; p++)
            wq[p] = *reinterpret_cast<const ulonglong2*>(
                &wrow[(tx + 16 * p) * WPIT + kk]);
#pragma unroll
        for (int q = 0; q < 4; q++)
#pragma unroll
            for (int p = 0; p < 8; p++) {
                acc[q][p] = fma2(xq[q].x, wq[p].x, acc[q][p]);
                acc[q][p] = fma2(xq[q].y, wq[p].y, acc[q][p]);
            }
    }

    // ---- writeout: horizontal add, scalar STG ----
#pragma unroll
    for (int q = 0; q < 4; q++) {
        float* op = g_xproj + (row0 + ty * 4 + q) * NGATE;
#pragma unroll
        for (int p = 0; p < 8; p++) {
            float lo, hi;
            unpack2(acc[q][p], lo, hi);
            op[tx + 16 * p] = lo + hi;
        }
    }
}

// ============================================================================
// Kernel B: recurrence, single-warp CTA, 1 sample, barrier-free.
// Thread t owns all four gates of cell t (rows t, t+32, t+64, t+96) so the
// cell-state update is thread-local. h broadcast via 128 B of smem.
// ============================================================================
__global__ void __launch_bounds__(32)
recur_kernel(const float* __restrict__ W_hh,
             const float* __restrict__ W_d,
             const float* __restrict__ b_d,
             float* __restrict__ out)
{
    __shared__ ull hp[HID / 2];    // h as k-pairs, 128 B

    const int t = threadIdx.x;     // lane = cell index
    const int b = blockIdx.x;      // sample

    // weights for rows t, t+32, t+64, t+96, packed along k (ull reinterpret
    // of row-major W_hh rows; rows are 128 B so 8B-aligned)
    ull wI[16], wF[16], wG[16], wO[16];
    {
        const ull* wr = reinterpret_cast<const ull*>(W_hh);
#pragma unroll
        for (int kk = 0; kk < 16; kk++) {
            wI[kk] = wr[(t)      * 16 + kk];
            wF[kk] = wr[(t + 32) * 16 + kk];
            wG[kk] = wr[(t + 64) * 16 + kk];
            wO[kk] = wr[(t + 96) * 16 + kk];
        }
    }

    if (t < HID / 2) hp[t] = 0ULL;
    float c = 0.0f;

    const float* xpp = g_xproj + (size_t)b * NGATE;
    const size_t step_stride = (size_t)BATCH * NGATE;

    float xpI = xpp[t];
    float xpF = xpp[t + 32];
    float xpG = xpp[t + 64];
    float xpO = xpp[t + 96];
    __syncwarp();

    for (int ts = 0; ts < T_STEPS; ts++) {
        // prefetch next step's x_proj (4 coalesced 128B segments per warp)
        float xnI, xnF, xnG, xnO;
        const bool has_next = (ts + 1 < T_STEPS);
        if (has_next) {
            const float* xn = xpp + (size_t)(ts + 1) * step_stride;
            xnI = xn[t];
            xnF = xn[t + 32];
            xnG = xn[t + 64];
            xnO = xn[t + 96];
        }

        // phase 1: 4 gate rows, 16 k-pairs, h broadcast from smem
        ull aI = pack2(xpI, 0.0f);
        ull aF = pack2(xpF, 0.0f);
        ull aG = pack2(xpG, 0.0f);
        ull aO = pack2(xpO, 0.0f);
#pragma unroll
        for (int kk = 0; kk < 16; kk++) {
            const ull hv = hp[kk];
            aI = fma2(hv, wI[kk], aI);
            aF = fma2(hv, wF[kk], aF);
            aG = fma2(hv, wG[kk], aG);
            aO = fma2(hv, wO[kk], aO);
        }
        float lo, hi;
        unpack2(aI, lo, hi); const float ig = sigm_fast(lo + hi);
        unpack2(aF, lo, hi); const float fg = sigm_fast(lo + hi);
        unpack2(aG, lo, hi); const float gg = tanh_fast(lo + hi);
        unpack2(aO, lo, hi); const float og = sigm_fast(lo + hi);

        __syncwarp();   // all lanes done reading hp of this step

        // phase 2: thread-local cell update
        c = fg * c + ig * gg;
        const float h = og * tanh_fast(c);
        reinterpret_cast<float*>(hp)[t] = h;

        __syncwarp();   // h visible for next step

        if (has_next) { xpI = xnI; xpF = xnF; xpG = xnG; xpO = xnO; }
    }

    // epilogue: out[b, a] = relu(h_T) @ W_d^T + b_d
    if (t < 3) {
        float sum = b_d[t];
        const float* hf = reinterpret_cast<const float*>(hp);
#pragma unroll
        for (int j = 0; j < HID; j++)
            sum += fmaxf(hf[j], 0.0f) * W_d[t * HID + j];
        out[(size_t)b * 3 + t] = sum;
    }
}

extern "C" void kernel_launch(void* const* d_in, const int* in_sizes, int n_in,
                              void* d_out, int out_size)
{
    const float* x    = (const float*)d_in[0];
    const float* W_ih = (const float*)d_in[1];
    const float* W_hh = (const float*)d_in[2];
    const float* b_ih = (const float*)d_in[3];
    const float* b_hh = (const float*)d_in[4];
    const float* W_d  = (const float*)d_in[5];
    const float* b_d  = (const float*)d_in[6];
    float* out = (float*)d_out;

    // Kernel A: x_proj GEMM over all timesteps (no recurrence)
    {
        dim3 grid((T_STEPS * BATCH) / XS);   // 16384 CTAs
        dim3 block(256);
        xproj_kernel<<<grid, block>>>(x, W_ih, b_ih, b_hh);
    }
    // Kernel B: sequential LSTM recurrence + decode head
    {
        dim3 grid(BATCH);                    // 2048 single-warp CTAs
        dim3 block(32);
        recur_kernel<<<grid, block>>>(W_hh, W_d, b_d, out);
    }
}

// round 6
// speedup vs baseline: 2.1365x; 1.1151x over previous
#include <cuda_runtime.h>
#include <cstdint>

#define T_STEPS 512
#define BATCH   2048
#define F_IN    64
#define HID     32
#define NGATE   128   // 4*HID
#define PFD     3     // prefetch distance (steps)

typedef unsigned long long ull;

// x_proj scratch, CELL-MAJOR gate quads: entry [t][b][cell*4 + gtype].
// Padded by 4 steps so distance-PFD prefetch never reads out of bounds.
__device__ float g_xproj[(size_t)(T_STEPS + 4) * BATCH * NGATE];

__device__ __forceinline__ ull pack2(float lo, float hi) {
    ull r;
    asm("mov.b64 %0, {%1,%2};" : "=l"(r) : "f"(lo), "f"(hi));
    return r;
}
__device__ __forceinline__ void unpack2(ull p, float &lo, float &hi) {
    asm("mov.b64 {%0,%1}, %2;" : "=f"(lo), "=f"(hi) : "l"(p));
}
// packed f32x2 fma: d = a*b + c (lane-wise)
__device__ __forceinline__ ull fma2(ull a, ull b, ull c) {
    ull d;
    asm("fma.rn.f32x2 %0, %1, %2, %3;" : "=l"(d) : "l"(a), "l"(b), "l"(c));
    return d;
}

__device__ __forceinline__ float tanh_fast(float x) {
    float y;
    asm("tanh.approx.f32 %0, %1;" : "=f"(y) : "f"(x));
    return y;
}
__device__ __forceinline__ float sigm_fast(float x) {
    return fmaf(0.5f, tanh_fast(0.5f * x), 0.5f);
}

// ============================================================================
// Kernel A: x_proj = x @ W_ih^T + (b_ih + b_hh)   -- [1M, 64] x [64, 128]
// k lives in the f32x2 lanes. Coalesced float4 staging for both operands.
// CTA tile: 64 samples x 128 gates (256 thr); thread tile 4s x 8g.
// Writeout is CELL-MAJOR: quad (i,f,g,o) of cell c at float4 index c.
// ============================================================================
#define XS   64     // samples per CTA
#define WPIT 34     // ull pitch (32 data + 2 pad)

__global__ void __launch_bounds__(256)
xproj_kernel(const float* __restrict__ x,
             const float* __restrict__ W_ih,
             const float* __restrict__ b_ih,
             const float* __restrict__ b_hh)
{
    __shared__ __align__(16) ull wrow[NGATE * WPIT];  // 34816 B
    __shared__ __align__(16) ull xrow[XS * WPIT];     // 17408 B

    const int t  = threadIdx.x;
    const int tx = t & 15;               // gates: tx + 16p, p=0..7
    const int ty = t >> 4;               // samples: ty*4 .. ty*4+3
    const size_t row0 = (size_t)blockIdx.x * XS;

    // ---- stage W (32 KB) coalesced: 8 float4/thread ----
    {
        const float4* wg = reinterpret_cast<const float4*>(W_ih);
#pragma unroll
        for (int i = 0; i < 8; i++) {
            const int idx = t + 256 * i;      // float4 index, g-major
            const int g = idx >> 4;
            const int c = idx & 15;
            const float4 v = wg[idx];
            *reinterpret_cast<ulonglong2*>(&wrow[g * WPIT + 2 * c]) =
                make_ulonglong2(pack2(v.x, v.y), pack2(v.z, v.w));
        }
    }
    // ---- stage x tile (16 KB) coalesced: 4 float4/thread ----
    {
        const float4* xg = reinterpret_cast<const float4*>(x + row0 * F_IN);
#pragma unroll
        for (int i = 0; i < 4; i++) {
            const int idx = t + 256 * i;
            const int s = idx >> 4;
            const int c = idx & 15;
            const float4 v = xg[idx];
            *reinterpret_cast<ulonglong2*>(&xrow[s * WPIT + 2 * c]) =
                make_ulonglong2(pack2(v.x, v.y), pack2(v.z, v.w));
        }
    }

    // ---- acc init with bias in lo lane ----
    ull acc[4][8];
    {
#pragma unroll
        for (int p = 0; p < 8; p++) {
            const int g = tx + 16 * p;
            const ull b = pack2(b_ih[g] + b_hh[g], 0.0f);
#pragma unroll
            for (int q = 0; q < 4; q++) acc[q][p] = b;
        }
    }
    __syncthreads();

    // ---- main loop: per 2 kk: 12 LDS.128 feed 64 FFMA2 ----
#pragma unroll 4
    for (int kk = 0; kk < 32; kk += 2) {
        ulonglong2 xq[4], wq[8];
#pragma unroll
        for (int q = 0; q < 4; q++)
            xq[q] = *reinterpret_cast<const ulonglong2*>(
                &xrow[(ty * 4 + q) * WPIT + kk]);
#pragma unroll
        for (int p = 0; p < 8; p++)
            wq[p] = *reinterpret_cast<const ulonglong2*>(
                &wrow[(tx + 16 * p) * WPIT + kk]);
#pragma unroll
        for (int q = 0; q < 4; q++)
#pragma unroll
            for (int p = 0; p < 8; p++) {
                acc[q][p] = fma2(xq[q].x, wq[p].x, acc[q][p]);
                acc[q][p] = fma2(xq[q].y, wq[p].y, acc[q][p]);
            }
    }

    // ---- writeout: cell-major gate quads, coalesced STG.128 ----
    // gate g = tx+16p -> cell (g&31), type (g>>5). p even -> cell tx,
    // p odd -> cell tx+16; p/2 = gate type. Two float4 per sample.
#pragma unroll
    for (int q = 0; q < 4; q++) {
        float o[8];
#pragma unroll
        for (int p = 0; p < 4; p++)
            unpack2(acc[q][p], o[2 * p], o[2 * p + 1]);
        float hlo, hhi;
        float4 v0, v1;
        unpack2(acc[q][0], hlo, hhi); v0.x = hlo + hhi;   // type 0, cell tx
        unpack2(acc[q][2], hlo, hhi); v0.y = hlo + hhi;   // type 1
        unpack2(acc[q][4], hlo, hhi); v0.z = hlo + hhi;   // type 2
        unpack2(acc[q][6], hlo, hhi); v0.w = hlo + hhi;   // type 3
        unpack2(acc[q][1], hlo, hhi); v1.x = hlo + hhi;   // cell tx+16
        unpack2(acc[q][3], hlo, hhi); v1.y = hlo + hhi;
        unpack2(acc[q][5], hlo, hhi); v1.z = hlo + hhi;
        unpack2(acc[q][7], hlo, hhi); v1.w = hlo + hhi;
        float4* op4 = reinterpret_cast<float4*>(
            g_xproj + (row0 + ty * 4 + q) * NGATE);
        op4[tx]      = v0;
        op4[tx + 16] = v1;
    }
}

// ============================================================================
// Kernel B: recurrence, single-warp CTA, 1 sample, barrier-free.
// Lane t owns cell t (gate rows t, t+32, t+64, t+96). Per step:
// 1 LDG.128 (prefetch dist PFD), 8 LDS.128 (h pairs), 64 FFMA2, 5 MUFU,
// 1 STS, 1 SYNCWARP (double-buffered h).
// ============================================================================
__global__ void __launch_bounds__(32)
recur_kernel(const float* __restrict__ W_hh,
             const float* __restrict__ W_d,
             const float* __restrict__ b_d,
             float* __restrict__ out)
{
    __shared__ ull hp[2][HID / 2];    // double-buffered h pairs, 256 B

    const int t = threadIdx.x;        // lane = cell index
    const int b = blockIdx.x;         // sample

    // weight rows t, t+32, t+64, t+96 packed along k
    ull wI[16], wF[16], wG[16], wO[16];
    {
        const ull* wr = reinterpret_cast<const ull*>(W_hh);
#pragma unroll
        for (int kk = 0; kk < 16; kk++) {
            wI[kk] = wr[(t)      * 16 + kk];
            wF[kk] = wr[(t + 32) * 16 + kk];
            wG[kk] = wr[(t + 64) * 16 + kk];
            wO[kk] = wr[(t + 96) * 16 + kk];
        }
    }

    if (t < HID / 2) hp[0][t] = 0ULL;
    float c = 0.0f;

    const float4* xq = reinterpret_cast<const float4*>(
        g_xproj + (size_t)b * NGATE) + t;
    const size_t step_stride4 = (size_t)BATCH * NGATE / 4;

    // prefetch pipeline: cur = step ts, p1 = ts+1, p2 = ts+2
    float4 cur = xq[0];
    float4 p1  = xq[step_stride4];
    float4 p2  = xq[2 * step_stride4];
    __syncwarp();

#pragma unroll 2
    for (int ts = 0; ts < T_STEPS; ts++) {
        // issue load for ts+PFD (padded region beyond T_STEPS: loaded, unused)
        const float4 nx = xq[(size_t)(ts + PFD) * step_stride4];

        const int rb = ts & 1;
        const ulonglong2* hq2 = reinterpret_cast<const ulonglong2*>(hp[rb]);

        // phase 1: 4 gate rows, h broadcast from smem
        ull aI = pack2(cur.x, 0.0f);
        ull aF = pack2(cur.y, 0.0f);
        ull aG = pack2(cur.z, 0.0f);
        ull aO = pack2(cur.w, 0.0f);
#pragma unroll
        for (int k2 = 0; k2 < 8; k2++) {
            const ulonglong2 hv = hq2[k2];
            aI = fma2(hv.x, wI[2 * k2], aI);
            aF = fma2(hv.x, wF[2 * k2], aF);
            aG = fma2(hv.x, wG[2 * k2], aG);
            aO = fma2(hv.x, wO[2 * k2], aO);
            aI = fma2(hv.y, wI[2 * k2 + 1], aI);
            aF = fma2(hv.y, wF[2 * k2 + 1], aF);
            aG = fma2(hv.y, wG[2 * k2 + 1], aG);
            aO = fma2(hv.y, wO[2 * k2 + 1], aO);
        }
        float lo, hi;
        unpack2(aI, lo, hi); const float ig = sigm_fast(lo + hi);
        unpack2(aF, lo, hi); const float fg = sigm_fast(lo + hi);
        unpack2(aG, lo, hi); const float gg = tanh_fast(lo + hi);
        unpack2(aO, lo, hi); const float og = sigm_fast(lo + hi);

        // phase 2: thread-local cell update, write to OTHER buffer
        c = fg * c + ig * gg;
        const float h = og * tanh_fast(c);
        reinterpret_cast<float*>(hp[1 - rb])[t] = h;

        __syncwarp();   // h buffer (1-rb) visible for next step's reads

        cur = p1; p1 = p2; p2 = nx;   // rotate prefetch pipeline
    }

    // epilogue: out[b, a] = relu(h_T) @ W_d^T + b_d
    // final h lives in buffer written at ts=T-1: 1-((T-1)&1) = T&1 = 0
    if (t < 3) {
        float sum = b_d[t];
        const float* hf = reinterpret_cast<const float*>(hp[T_STEPS & 1]);
#pragma unroll
        for (int j = 0; j < HID; j++)
            sum += fmaxf(hf[j], 0.0f) * W_d[t * HID + j];
        out[(size_t)b * 3 + t] = sum;
    }
}

extern "C" void kernel_launch(void* const* d_in, const int* in_sizes, int n_in,
                              void* d_out, int out_size)
{
    const float* x    = (const float*)d_in[0];
    const float* W_ih = (const float*)d_in[1];
    const float* W_hh = (const float*)d_in[2];
    const float* b_ih = (const float*)d_in[3];
    const float* b_hh = (const float*)d_in[4];
    const float* W_d  = (const float*)d_in[5];
    const float* b_d  = (const float*)d_in[6];
    float* out = (float*)d_out;

    // Kernel A: x_proj GEMM over all timesteps (no recurrence)
    {
        dim3 grid((T_STEPS * BATCH) / XS);   // 16384 CTAs
        dim3 block(256);
        xproj_kernel<<<grid, block>>>(x, W_ih, b_ih, b_hh);
    }
    // Kernel B: sequential LSTM recurrence + decode head
    {
        dim3 grid(BATCH);                    // 2048 single-warp CTAs
        dim3 block(32);
        recur_kernel<<<grid, block>>>(W_hh, W_d, b_d, out);
    }
}

// round 7
// speedup vs baseline: 2.5821x; 1.2086x over previous
#include <cuda_runtime.h>
#include <cstdint>

#define T_STEPS 512
#define BATCH   2048
#define F_IN    64
#define HID     32
#define NGATE   128   // 4*HID
#define PFD     3     // prefetch distance (steps)

typedef unsigned long long ull;

// x_proj scratch, CELL-MAJOR gate quads: entry [t][b][cell*4 + gtype].
// Padded by 4 steps so distance-PFD prefetch never reads out of bounds.
__device__ float g_xproj[(size_t)(T_STEPS + 4) * BATCH * NGATE];

__device__ __forceinline__ ull pack2(float lo, float hi) {
    ull r;
    asm("mov.b64 %0, {%1,%2};" : "=l"(r) : "f"(lo), "f"(hi));
    return r;
}
__device__ __forceinline__ void unpack2(ull p, float &lo, float &hi) {
    asm("mov.b64 {%0,%1}, %2;" : "=f"(lo), "=f"(hi) : "l"(p));
}
// packed f32x2 fma: d = a*b + c (lane-wise)
__device__ __forceinline__ ull fma2(ull a, ull b, ull c) {
    ull d;
    asm("fma.rn.f32x2 %0, %1, %2, %3;" : "=l"(d) : "l"(a), "l"(b), "l"(c));
    return d;
}

__device__ __forceinline__ float tanh_fast(float x) {
    float y;
    asm("tanh.approx.f32 %0, %1;" : "=f"(y) : "f"(x));
    return y;
}
__device__ __forceinline__ float sigm_fast(float x) {
    return fmaf(0.5f, tanh_fast(0.5f * x), 0.5f);
}

// ============================================================================
// Kernel A: x_proj = x @ W_ih^T + (b_ih + b_hh)   -- [1M, 64] x [64, 128]
// (unchanged from round 6)
// ============================================================================
#define XS   64     // samples per CTA
#define WPIT 34     // ull pitch (32 data + 2 pad)

__global__ void __launch_bounds__(256)
xproj_kernel(const float* __restrict__ x,
             const float* __restrict__ W_ih,
             const float* __restrict__ b_ih,
             const float* __restrict__ b_hh)
{
    __shared__ __align__(16) ull wrow[NGATE * WPIT];  // 34816 B
    __shared__ __align__(16) ull xrow[XS * WPIT];     // 17408 B

    const int t  = threadIdx.x;
    const int tx = t & 15;               // gates: tx + 16p, p=0..7
    const int ty = t >> 4;               // samples: ty*4 .. ty*4+3
    const size_t row0 = (size_t)blockIdx.x * XS;

    // ---- stage W (32 KB) coalesced: 8 float4/thread ----
    {
        const float4* wg = reinterpret_cast<const float4*>(W_ih);
#pragma unroll
        for (int i = 0; i < 8; i++) {
            const int idx = t + 256 * i;      // float4 index, g-major
            const int g = idx >> 4;
            const int c = idx & 15;
            const float4 v = wg[idx];
            *reinterpret_cast<ulonglong2*>(&wrow[g * WPIT + 2 * c]) =
                make_ulonglong2(pack2(v.x, v.y), pack2(v.z, v.w));
        }
    }
    // ---- stage x tile (16 KB) coalesced: 4 float4/thread ----
    {
        const float4* xg = reinterpret_cast<const float4*>(x + row0 * F_IN);
#pragma unroll
        for (int i = 0; i < 4; i++) {
            const int idx = t + 256 * i;
            const int s = idx >> 4;
            const int c = idx & 15;
            const float4 v = xg[idx];
            *reinterpret_cast<ulonglong2*>(&xrow[s * WPIT + 2 * c]) =
                make_ulonglong2(pack2(v.x, v.y), pack2(v.z, v.w));
        }
    }

    // ---- acc init with bias in lo lane ----
    ull acc[4][8];
    {
#pragma unroll
        for (int p = 0; p < 8; p++) {
            const int g = tx + 16 * p;
            const ull b = pack2(b_ih[g] + b_hh[g], 0.0f);
#pragma unroll
            for (int q = 0; q < 4; q++) acc[q][p] = b;
        }
    }
    __syncthreads();

    // ---- main loop: per 2 kk: 12 LDS.128 feed 64 FFMA2 ----
#pragma unroll 4
    for (int kk = 0; kk < 32; kk += 2) {
        ulonglong2 xq[4], wq[8];
#pragma unroll
        for (int q = 0; q < 4; q++)
            xq[q] = *reinterpret_cast<const ulonglong2*>(
                &xrow[(ty * 4 + q) * WPIT + kk]);
#pragma unroll
        for (int p = 0; p < 8; p++)
            wq[p] = *reinterpret_cast<const ulonglong2*>(
                &wrow[(tx + 16 * p) * WPIT + kk]);
#pragma unroll
        for (int q = 0; q < 4; q++)
#pragma unroll
            for (int p = 0; p < 8; p++) {
                acc[q][p] = fma2(xq[q].x, wq[p].x, acc[q][p]);
                acc[q][p] = fma2(xq[q].y, wq[p].y, acc[q][p]);
            }
    }

    // ---- writeout: cell-major gate quads, coalesced STG.128 ----
#pragma unroll
    for (int q = 0; q < 4; q++) {
        float hlo, hhi;
        float4 v0, v1;
        unpack2(acc[q][0], hlo, hhi); v0.x = hlo + hhi;   // type 0, cell tx
        unpack2(acc[q][2], hlo, hhi); v0.y = hlo + hhi;   // type 1
        unpack2(acc[q][4], hlo, hhi); v0.z = hlo + hhi;   // type 2
        unpack2(acc[q][6], hlo, hhi); v0.w = hlo + hhi;   // type 3
        unpack2(acc[q][1], hlo, hhi); v1.x = hlo + hhi;   // cell tx+16
        unpack2(acc[q][3], hlo, hhi); v1.y = hlo + hhi;
        unpack2(acc[q][5], hlo, hhi); v1.z = hlo + hhi;
        unpack2(acc[q][7], hlo, hhi); v1.w = hlo + hhi;
        float4* op4 = reinterpret_cast<float4*>(
            g_xproj + (row0 + ty * 4 + q) * NGATE);
        op4[tx]      = v0;
        op4[tx + 16] = v1;
    }
}

// ============================================================================
// Kernel B: recurrence, single-warp CTA, TWO samples per warp.
// Lane t owns cell t of both samples (weights shared in registers).
// Prefetch ring buf[4] with fully-unrolled x4 body -> pure register renaming,
// loads for ts+3 stay in flight ~3 steps. One SYNCWARP/step (double-buffered h).
// ============================================================================
__global__ void __launch_bounds__(32)
recur_kernel(const float* __restrict__ W_hh,
             const float* __restrict__ W_d,
             const float* __restrict__ b_d,
             float* __restrict__ out)
{
    __shared__ ull hp[2][2][HID / 2];   // [buf][sample][kpair], 512 B

    const int t  = threadIdx.x;         // lane = cell index
    const int bA = blockIdx.x * 2;      // samples bA, bA+1

    // weight rows t, t+32, t+64, t+96 packed along k (shared by both samples)
    ull wI[16], wF[16], wG[16], wO[16];
    {
        const ull* wr = reinterpret_cast<const ull*>(W_hh);
#pragma unroll
        for (int kk = 0; kk < 16; kk++) {
            wI[kk] = wr[(t)      * 16 + kk];
            wF[kk] = wr[(t + 32) * 16 + kk];
            wG[kk] = wr[(t + 64) * 16 + kk];
            wO[kk] = wr[(t + 96) * 16 + kk];
        }
    }

    if (t < HID / 2) { hp[0][0][t] = 0ULL; hp[0][1][t] = 0ULL; }
    float cA = 0.0f, cB = 0.0f;

    const float4* xqA = reinterpret_cast<const float4*>(
        g_xproj + (size_t)bA * NGATE) + t;
    const float4* xqB = xqA + NGATE / 4;
    const size_t s4 = (size_t)BATCH * NGATE / 4;   // float4 step stride

    // prefetch ring: buf[i&3] holds step i's quad
    float4 bufA[4], bufB[4];
    bufA[0] = xqA[0];       bufB[0] = xqB[0];
    bufA[1] = xqA[s4];      bufB[1] = xqB[s4];
    bufA[2] = xqA[2 * s4];  bufB[2] = xqB[2 * s4];
    __syncwarp();

#pragma unroll 1
    for (int ts0 = 0; ts0 < T_STEPS; ts0 += 4) {
#pragma unroll
        for (int u = 0; u < 4; u++) {
            const int ts = ts0 + u;
            // issue loads for ts+PFD into ring slot (constant index per body)
            bufA[(ts + PFD) & 3] = xqA[(size_t)(ts + PFD) * s4];
            bufB[(ts + PFD) & 3] = xqB[(size_t)(ts + PFD) * s4];

            const float4 curA = bufA[ts & 3];
            const float4 curB = bufB[ts & 3];
            const int rb = ts & 1;
            const ulonglong2* hqA = reinterpret_cast<const ulonglong2*>(hp[rb][0]);
            const ulonglong2* hqB = reinterpret_cast<const ulonglong2*>(hp[rb][1]);

            // phase 1: 4 gate rows x 2 samples, h broadcast from smem
            ull aIA = pack2(curA.x, 0.0f), aFA = pack2(curA.y, 0.0f);
            ull aGA = pack2(curA.z, 0.0f), aOA = pack2(curA.w, 0.0f);
            ull aIB = pack2(curB.x, 0.0f), aFB = pack2(curB.y, 0.0f);
            ull aGB = pack2(curB.z, 0.0f), aOB = pack2(curB.w, 0.0f);
#pragma unroll
            for (int k2 = 0; k2 < 8; k2++) {
                const ulonglong2 hvA = hqA[k2];
                const ulonglong2 hvB = hqB[k2];
                aIA = fma2(hvA.x, wI[2 * k2], aIA);
                aIB = fma2(hvB.x, wI[2 * k2], aIB);
                aFA = fma2(hvA.x, wF[2 * k2], aFA);
                aFB = fma2(hvB.x, wF[2 * k2], aFB);
                aGA = fma2(hvA.x, wG[2 * k2], aGA);
                aGB = fma2(hvB.x, wG[2 * k2], aGB);
                aOA = fma2(hvA.x, wO[2 * k2], aOA);
                aOB = fma2(hvB.x, wO[2 * k2], aOB);
                aIA = fma2(hvA.y, wI[2 * k2 + 1], aIA);
                aIB = fma2(hvB.y, wI[2 * k2 + 1], aIB);
                aFA = fma2(hvA.y, wF[2 * k2 + 1], aFA);
                aFB = fma2(hvB.y, wF[2 * k2 + 1], aFB);
                aGA = fma2(hvA.y, wG[2 * k2 + 1], aGA);
                aGB = fma2(hvB.y, wG[2 * k2 + 1], aGB);
                aOA = fma2(hvA.y, wO[2 * k2 + 1], aOA);
                aOB = fma2(hvB.y, wO[2 * k2 + 1], aOB);
            }
            float lo, hi;
            unpack2(aIA, lo, hi); const float igA = sigm_fast(lo + hi);
            unpack2(aIB, lo, hi); const float igB = sigm_fast(lo + hi);
            unpack2(aFA, lo, hi); const float fgA = sigm_fast(lo + hi);
            unpack2(aFB, lo, hi); const float fgB = sigm_fast(lo + hi);
            unpack2(aGA, lo, hi); const float ggA = tanh_fast(lo + hi);
            unpack2(aGB, lo, hi); const float ggB = tanh_fast(lo + hi);
            unpack2(aOA, lo, hi); const float ogA = sigm_fast(lo + hi);
            unpack2(aOB, lo, hi); const float ogB = sigm_fast(lo + hi);

            // phase 2: thread-local cell updates, write to OTHER buffer
            cA = fgA * cA + igA * ggA;
            cB = fgB * cB + igB * ggB;
            const float hA = ogA * tanh_fast(cA);
            const float hB = ogB * tanh_fast(cB);
            reinterpret_cast<float*>(hp[1 - rb][0])[t] = hA;
            reinterpret_cast<float*>(hp[1 - rb][1])[t] = hB;

            __syncwarp();   // h buffer (1-rb) visible for next step
        }
    }

    // epilogue: out[b, a] = relu(h_T) @ W_d^T + b_d
    // final h in buffer 1-((T-1)&1) = T&1 = 0
    if ((t & 3) < 3 && t < 8) {
        const int s = t >> 2;       // 0 = sample A, 1 = sample B
        const int a = t & 3;        // action
        float sum = b_d[a];
        const float* hf = reinterpret_cast<const float*>(hp[T_STEPS & 1][s]);
#pragma unroll
        for (int j = 0; j < HID; j++)
            sum += fmaxf(hf[j], 0.0f) * W_d[a * HID + j];
        out[(size_t)(bA + s) * 3 + a] = sum;
    }
}

extern "C" void kernel_launch(void* const* d_in, const int* in_sizes, int n_in,
                              void* d_out, int out_size)
{
    const float* x    = (const float*)d_in[0];
    const float* W_ih = (const float*)d_in[1];
    const float* W_hh = (const float*)d_in[2];
    const float* b_ih = (const float*)d_in[3];
    const float* b_hh = (const float*)d_in[4];
    const float* W_d  = (const float*)d_in[5];
    const float* b_d  = (const float*)d_in[6];
    float* out = (float*)d_out;

    // Kernel A: x_proj GEMM over all timesteps (no recurrence)
    {
        dim3 grid((T_STEPS * BATCH) / XS);   // 16384 CTAs
        dim3 block(256);
        xproj_kernel<<<grid, block>>>(x, W_ih, b_ih, b_hh);
    }
    // Kernel B: sequential LSTM recurrence + decode head
    {
        dim3 grid(BATCH / 2);                // 1024 single-warp CTAs
        dim3 block(32);
        recur_kernel<<<grid, block>>>(W_hh, W_d, b_d, out);
    }
}